// round 3
// baseline (speedup 1.0000x reference)
#include <cuda_runtime.h>
#include <cstdint>

// Problem dims
#define NIMG 32
#define CCH 16
#define HH 224
#define WW 224
#define HWSZ (HH*WW)          // 50176
#define NPIX (NIMG*HWSZ)      // 1,605,632 pixels
#define TOTAL (NIMG*CCH*HWSZ) // 25,690,112 elements

// Conv tiling: 16x32 pixel tile, 256 threads, 2 warp-groups of 8 oc each,
// 4 pixels per thread (column-strided by 8 for conflict-free LDS + coalesced STG)
#define TH 16
#define TW 32
#define GX (WW/TW)   // 7
#define GY (HH/TH)   // 14

// ---------------- scratch (device globals: no allocations allowed) ----------
__device__ unsigned           g_maxbits;     // max|x| as float bits (all >= 0)
__device__ float              g_stepw;       // weight quant step
__device__ int4               g_wq[16*9];    // packed int8 weights [oc][tap]
__device__ int4               g_xq[NPIX];    // packed int8 activations [n][h][w]
__device__ unsigned long long g_sumI[16];    // exact global sum of acc   (2's comp)
__device__ unsigned long long g_sumQ[16];    // exact global sum of acc^2
__device__ float              g_scale[16];   // fused BN scale (incl. stepx*stepw)
__device__ float              g_bias[16];    // fused BN bias

// ---------------- k_init: reset + weight max + weight quantize/pack ---------
__global__ void k_init(const float* __restrict__ w) {
    __shared__ float red[256];
    __shared__ float s_stepw;
    int t = threadIdx.x;
    if (t == 0) g_maxbits = 0u;
    if (t < 16) { g_sumI[t] = 0ull; g_sumQ[t] = 0ull; }
    float m = 0.f;
    for (int i = t; i < 16*16*9; i += 256) m = fmaxf(m, fabsf(w[i]));
    red[t] = m; __syncthreads();
    for (int s = 128; s; s >>= 1) {
        if (t < s) red[t] = fmaxf(red[t], red[t+s]);
        __syncthreads();
    }
    if (t == 0) {
        float sw = __fdiv_rn(red[0], 127.0f);
        g_stepw = sw; s_stepw = sw;
    }
    __syncthreads();
    float sw = s_stepw;
    if (t < 144) {                       // 16 oc * 9 taps
        int oc = t / 9, tap = t % 9;
        int vals[4];
        #pragma unroll
        for (int g = 0; g < 4; ++g) {
            int packed = 0;
            #pragma unroll
            for (int b = 0; b < 4; ++b) {
                int c = g*4 + b;
                float v = w[(oc*16 + c)*9 + tap];
                float q = rintf(__fdiv_rn(v, sw));
                q = fminf(fmaxf(q, -127.f), 127.f);
                int qi = (int)q;
                packed |= (qi & 0xFF) << (8*b);
            }
            vals[g] = packed;
        }
        g_wq[oc*9 + tap] = make_int4(vals[0], vals[1], vals[2], vals[3]);
    }
}

// ---------------- k_xmax: global max|x| ------------------------------------
__global__ void k_xmax(const float4* __restrict__ x) {
    float m = 0.f;
    int stride = gridDim.x * blockDim.x;
    for (int i = blockIdx.x*blockDim.x + threadIdx.x; i < TOTAL/4; i += stride) {
        float4 v = x[i];
        m = fmaxf(m, fmaxf(fmaxf(fabsf(v.x), fabsf(v.y)), fmaxf(fabsf(v.z), fabsf(v.w))));
    }
    #pragma unroll
    for (int off = 16; off; off >>= 1)
        m = fmaxf(m, __shfl_xor_sync(0xFFFFFFFFu, m, off));
    __shared__ float red[8];
    int lane = threadIdx.x & 31, wp = threadIdx.x >> 5;
    if (lane == 0) red[wp] = m;
    __syncthreads();
    if (threadIdx.x == 0) {
        float mm = red[0];
        #pragma unroll
        for (int i = 1; i < 8; ++i) mm = fmaxf(mm, red[i]);
        atomicMax(&g_maxbits, __float_as_uint(mm));
    }
}

// ---------------- k_xq: quantize x -> packed int8, 4 pixels per thread ------
__global__ void k_xq(const float* __restrict__ x) {
    int p4 = blockIdx.x*blockDim.x + threadIdx.x;
    if (p4 >= NPIX/4) return;
    float sx = __fdiv_rn(__uint_as_float(g_maxbits), 127.0f);
    int n = p4 / (HWSZ/4);
    int rem4 = p4 - n*(HWSZ/4);
    const float* base = x + (size_t)n*(CCH*HWSZ) + rem4*4;
    int out[4][4];   // [pixel][channel-group]
    #pragma unroll
    for (int c = 0; c < 16; ++c) {
        float4 v = *(const float4*)(base + (size_t)c*HWSZ);
        float f[4] = {v.x, v.y, v.z, v.w};
        int g = c >> 2, b = c & 3;
        #pragma unroll
        for (int px = 0; px < 4; ++px) {
            float q = rintf(__fdiv_rn(f[px], sx));
            q = fminf(fmaxf(q, -127.f), 127.f);
            int qi = (int)q;
            if (b == 0) out[px][g] = (qi & 0xFF);
            else out[px][g] |= (qi & 0xFF) << (8*b);
        }
    }
    int pix = n*HWSZ + rem4*4;
    #pragma unroll
    for (int px = 0; px < 4; ++px)
        g_xq[pix + px] = make_int4(out[px][0], out[px][1], out[px][2], out[px][3]);
}

// ---------------- conv: dp4a, 8 oc x 4 px per thread ------------------------
template<bool WRITE>
__global__ void __launch_bounds__(256, 4) k_conv(float* __restrict__ out) {
    __shared__ int4 s_x[TH+2][TW+2];    // 18 x 34 int4 = 9792 B
    __shared__ int4 s_w[144];           // 2304 B
    __shared__ long long s_I[8][8];
    __shared__ long long s_Q[8][8];

    int t = threadIdx.x;
    int n = blockIdx.z;
    int h0 = blockIdx.y * TH, w0 = blockIdx.x * TW;

    // load halo tile (zero padded)
    for (int i = t; i < 18*34; i += 256) {
        int r = i / 34, cc = i - r*34;
        int gh = h0 - 1 + r, gw = w0 - 1 + cc;
        int4 v = make_int4(0,0,0,0);
        if ((unsigned)gh < (unsigned)HH && (unsigned)gw < (unsigned)WW)
            v = g_xq[n*HWSZ + gh*WW + gw];
        s_x[r][cc] = v;
    }
    if (t < 144) s_w[t] = g_wq[t];
    __syncthreads();

    int ocbase = (t >> 7) * 8;          // warp-group 0: oc 0-7, group 1: oc 8-15
    int wt = t & 127;
    int r = wt >> 3;                    // pixel row 0..15
    int c = wt & 7;                     // pixel cols c, c+8, c+16, c+24

    int acc[8][4];
    #pragma unroll
    for (int j = 0; j < 8; ++j)
        #pragma unroll
        for (int m = 0; m < 4; ++m) acc[j][m] = 0;

    #pragma unroll
    for (int m = 0; m < 4; ++m) {
        int cm = c + 8*m;
        #pragma unroll
        for (int ky = 0; ky < 3; ++ky) {
            // conflict-free: 8 consecutive lanes read 8 consecutive int4
            int4 a0 = s_x[r + ky][cm];
            int4 a1 = s_x[r + ky][cm + 1];
            int4 a2 = s_x[r + ky][cm + 2];
            #pragma unroll
            for (int kx = 0; kx < 3; ++kx) {
                int4 a = (kx == 0) ? a0 : (kx == 1) ? a1 : a2;
                int tap = ky*3 + kx;
                #pragma unroll
                for (int j = 0; j < 8; ++j) {
                    int4 wv = s_w[(ocbase + j)*9 + tap];   // broadcast
                    int rj = acc[j][m];
                    rj = __dp4a(a.x, wv.x, rj);
                    rj = __dp4a(a.y, wv.y, rj);
                    rj = __dp4a(a.z, wv.z, rj);
                    rj = __dp4a(a.w, wv.w, rj);
                    acc[j][m] = rj;
                }
            }
        }
    }

    if (WRITE) {
        int h = h0 + r;
        size_t ob = (size_t)n*CCH*HWSZ + (size_t)h*WW + w0 + c;
        #pragma unroll
        for (int j = 0; j < 8; ++j) {
            int oc = ocbase + j;
            float sc = g_scale[oc], bi = g_bias[oc];
            size_t op = ob + (size_t)oc*HWSZ;
            #pragma unroll
            for (int m = 0; m < 4; ++m) {
                float y = fminf(fmaxf(fmaf((float)acc[j][m], sc, bi), 0.f), 6.f);
                out[op + 8*m] = y;
            }
        }
    } else {
        // exact per-channel integer stats
        int warp = t >> 5, lane = t & 31;
        #pragma unroll
        for (int j = 0; j < 8; ++j) {
            int s4 = acc[j][0] + acc[j][1] + acc[j][2] + acc[j][3];
            int si = __reduce_add_sync(0xFFFFFFFFu, s4);
            long long sq = 0;
            #pragma unroll
            for (int m = 0; m < 4; ++m)
                sq += (long long)acc[j][m] * (long long)acc[j][m];
            #pragma unroll
            for (int off = 16; off; off >>= 1)
                sq += __shfl_down_sync(0xFFFFFFFFu, sq, off);
            if (lane == 0) { s_I[warp][j] = (long long)si; s_Q[warp][j] = sq; }
        }
        __syncthreads();
        if (t < 16) {
            int grp = t >> 3, ocw = t & 7;   // warps grp*4..grp*4+3 hold oc t
            long long ti = 0, tq = 0;
            #pragma unroll
            for (int wp = 0; wp < 4; ++wp) {
                ti += s_I[grp*4 + wp][ocw];
                tq += s_Q[grp*4 + wp][ocw];
            }
            atomicAdd(&g_sumI[t], (unsigned long long)ti);
            atomicAdd(&g_sumQ[t], (unsigned long long)tq);
        }
    }
}

// ---------------- k_fin: compute BN affine from exact sums ------------------
__global__ void k_fin(const float* __restrict__ gamma, const float* __restrict__ beta) {
    int t = threadIdx.x;
    if (t < 16) {
        double stepx = (double)__fdiv_rn(__uint_as_float(g_maxbits), 127.0f);
        double sc = stepx * (double)g_stepw;      // y = sc * acc (exact)
        double M = (double)NPIX;
        double sumI = (double)(long long)g_sumI[t];
        double sumQ = (double)(long long)g_sumQ[t];
        double mean = sc * sumI / M;
        double ey2  = sc * sc * sumQ / M;
        double var  = ey2 - mean*mean;
        double inv  = (double)gamma[t] / sqrt(var + 1e-5);
        g_scale[t] = (float)(sc * inv);
        g_bias[t]  = (float)((double)beta[t] - mean * inv);
    }
}

// ---------------- launch ----------------------------------------------------
extern "C" void kernel_launch(void* const* d_in, const int* in_sizes, int n_in,
                              void* d_out, int out_size) {
    const float* x     = (const float*)d_in[0];
    const float* wgt   = (const float*)d_in[1];
    const float* gamma = (const float*)d_in[2];
    const float* beta  = (const float*)d_in[3];
    float* out = (float*)d_out;

    k_init<<<1, 256>>>(wgt);
    k_xmax<<<1184, 256>>>((const float4*)x);
    k_xq<<<(NPIX/4 + 255)/256, 256>>>(x);
    dim3 g(GX, GY, NIMG);
    k_conv<false><<<g, 256>>>(nullptr);
    k_fin<<<1, 32>>>(gamma, beta);
    k_conv<true><<<g, 256>>>(out);
}

// round 4
// speedup vs baseline: 1.7650x; 1.7650x over previous
#include <cuda_runtime.h>
#include <cstdint>

// Problem dims
#define NIMG 32
#define CCH 16
#define HH 224
#define WW 224
#define HWSZ (HH*WW)          // 50176
#define NPIX (NIMG*HWSZ)      // 1,605,632 pixels
#define TOTAL (NIMG*CCH*HWSZ) // 25,690,112 elements

// Conv tiling: 16x16 pixel tile, 256 threads, 2 warp-groups of 8 oc each
#define TH 16
#define TW 16
#define GX (WW/TW)   // 14
#define GY (HH/TH)   // 14

// ---------------- scratch (device globals: no allocations allowed) ----------
__device__ unsigned           g_maxbits;     // max|x| as float bits (all >= 0)
__device__ float              g_stepw;       // weight quant step
__device__ int4               g_wq[16*9];    // packed int8 weights [oc][tap]
__device__ int4               g_xq[NPIX];    // packed int8 activations [n][h][w]
__device__ unsigned long long g_sumI[16];    // exact global sum of acc   (2's comp)
__device__ unsigned long long g_sumQ[16];    // exact global sum of acc^2
__device__ float              g_scale[16];   // fused BN scale (incl. stepx*stepw)
__device__ float              g_bias[16];    // fused BN bias

// ---------------- k_init: reset + weight max + weight quantize/pack ---------
__global__ void k_init(const float* __restrict__ w) {
    __shared__ float red[256];
    __shared__ float s_stepw;
    int t = threadIdx.x;
    if (t == 0) g_maxbits = 0u;
    if (t < 16) { g_sumI[t] = 0ull; g_sumQ[t] = 0ull; }
    float m = 0.f;
    for (int i = t; i < 16*16*9; i += 256) m = fmaxf(m, fabsf(w[i]));
    red[t] = m; __syncthreads();
    for (int s = 128; s; s >>= 1) {
        if (t < s) red[t] = fmaxf(red[t], red[t+s]);
        __syncthreads();
    }
    if (t == 0) {
        float sw = __fdiv_rn(red[0], 127.0f);
        g_stepw = sw; s_stepw = sw;
    }
    __syncthreads();
    float sw = s_stepw;
    if (t < 144) {                       // 16 oc * 9 taps (only 144 divides: cheap)
        int oc = t / 9, tap = t % 9;
        int vals[4];
        #pragma unroll
        for (int g = 0; g < 4; ++g) {
            int packed = 0;
            #pragma unroll
            for (int b = 0; b < 4; ++b) {
                int c = g*4 + b;
                float v = w[(oc*16 + c)*9 + tap];
                float q = rintf(__fdiv_rn(v, sw));
                q = fminf(fmaxf(q, -127.f), 127.f);
                int qi = (int)q;
                packed |= (qi & 0xFF) << (8*b);
            }
            vals[g] = packed;
        }
        g_wq[oc*9 + tap] = make_int4(vals[0], vals[1], vals[2], vals[3]);
    }
}

// ---------------- k_xmax: global max|x| ------------------------------------
__global__ void k_xmax(const float4* __restrict__ x) {
    float m = 0.f;
    int stride = gridDim.x * blockDim.x;
    for (int i = blockIdx.x*blockDim.x + threadIdx.x; i < TOTAL/4; i += stride) {
        float4 v = x[i];
        m = fmaxf(m, fmaxf(fmaxf(fabsf(v.x), fabsf(v.y)), fmaxf(fabsf(v.z), fabsf(v.w))));
    }
    #pragma unroll
    for (int off = 16; off; off >>= 1)
        m = fmaxf(m, __shfl_xor_sync(0xFFFFFFFFu, m, off));
    __shared__ float red[8];
    int lane = threadIdx.x & 31, wp = threadIdx.x >> 5;
    if (lane == 0) red[wp] = m;
    __syncthreads();
    if (threadIdx.x == 0) {
        float mm = red[0];
        #pragma unroll
        for (int i = 1; i < 8; ++i) mm = fmaxf(mm, red[i]);
        atomicMax(&g_maxbits, __float_as_uint(mm));
    }
}

// ---------------- k_xq: quantize x -> packed int8, 4 pixels per thread ------
// One divide per thread; per-element quant is a single FMUL + RINT.
__global__ void k_xq(const float* __restrict__ x) {
    int p4 = blockIdx.x*blockDim.x + threadIdx.x;
    if (p4 >= NPIX/4) return;
    float sx  = __fdiv_rn(__uint_as_float(g_maxbits), 127.0f);  // step (matches ref)
    float inv = __fdiv_rn(1.0f, sx);                            // 1/step, <=1ulp off
    int n = p4 / (HWSZ/4);
    int rem4 = p4 - n*(HWSZ/4);
    const float* base = x + (size_t)n*(CCH*HWSZ) + rem4*4;
    int out[4][4];   // [pixel][channel-group]
    #pragma unroll
    for (int c = 0; c < 16; ++c) {
        float4 v = *(const float4*)(base + (size_t)c*HWSZ);
        float f[4] = {v.x, v.y, v.z, v.w};
        int g = c >> 2, b = c & 3;
        #pragma unroll
        for (int px = 0; px < 4; ++px) {
            float q = rintf(f[px] * inv);
            q = fminf(fmaxf(q, -127.f), 127.f);
            int qi = (int)q;
            if (b == 0) out[px][g] = (qi & 0xFF);
            else out[px][g] |= (qi & 0xFF) << (8*b);
        }
    }
    int pix = n*HWSZ + rem4*4;
    #pragma unroll
    for (int px = 0; px < 4; ++px)
        g_xq[pix + px] = make_int4(out[px][0], out[px][1], out[px][2], out[px][3]);
}

// ---------------- conv: dp4a, 8 oc x 2 pixels per thread --------------------
template<bool WRITE>
__global__ void __launch_bounds__(256, 4) k_conv(float* __restrict__ out) {
    __shared__ int4 s_x[TH+2][TW+2];    // 18 x 18 int4 = 5184 B
    __shared__ int4 s_w[144];           // 2304 B
    __shared__ long long s_I[8][8];
    __shared__ long long s_Q[8][8];

    int t = threadIdx.x;
    int n = blockIdx.z;
    int h0 = blockIdx.y * TH, w0 = blockIdx.x * TW;

    // load halo tile (zero padded)
    for (int i = t; i < 18*18; i += 256) {
        int r = i / 18, cc = i - r*18;
        int gh = h0 - 1 + r, gw = w0 - 1 + cc;
        int4 v = make_int4(0,0,0,0);
        if ((unsigned)gh < (unsigned)HH && (unsigned)gw < (unsigned)WW)
            v = g_xq[n*HWSZ + gh*WW + gw];
        s_x[r][cc] = v;
    }
    if (t < 144) s_w[t] = g_wq[t];
    __syncthreads();

    int ocbase = (t >> 7) * 8;          // warp-group 0: oc 0-7, group 1: oc 8-15
    int wt = t & 127;
    int r = wt >> 4, c = wt & 15;       // pixel rows r and r+8, col c

    int acc0[8], acc1[8];
    #pragma unroll
    for (int j = 0; j < 8; ++j) { acc0[j] = 0; acc1[j] = 0; }

    #pragma unroll
    for (int ky = 0; ky < 3; ++ky) {
        #pragma unroll
        for (int kx = 0; kx < 3; ++kx) {
            int4 a0 = s_x[r + ky][c + kx];
            int4 a1 = s_x[r + 8 + ky][c + kx];
            int tap = ky*3 + kx;
            #pragma unroll
            for (int j = 0; j < 8; ++j) {
                int4 wv = s_w[(ocbase + j)*9 + tap];
                int r0 = acc0[j], r1 = acc1[j];
                r0 = __dp4a(a0.x, wv.x, r0);
                r0 = __dp4a(a0.y, wv.y, r0);
                r0 = __dp4a(a0.z, wv.z, r0);
                r0 = __dp4a(a0.w, wv.w, r0);
                r1 = __dp4a(a1.x, wv.x, r1);
                r1 = __dp4a(a1.y, wv.y, r1);
                r1 = __dp4a(a1.z, wv.z, r1);
                r1 = __dp4a(a1.w, wv.w, r1);
                acc0[j] = r0; acc1[j] = r1;
            }
        }
    }

    if (WRITE) {
        int h = h0 + r, wcol = w0 + c;
        size_t ob = (size_t)n*CCH*HWSZ + (size_t)h*WW + wcol;
        #pragma unroll
        for (int j = 0; j < 8; ++j) {
            int oc = ocbase + j;
            float sc = g_scale[oc], bi = g_bias[oc];
            float y0 = fminf(fmaxf(fmaf((float)acc0[j], sc, bi), 0.f), 6.f);
            float y1 = fminf(fmaxf(fmaf((float)acc1[j], sc, bi), 0.f), 6.f);
            out[ob + (size_t)oc*HWSZ]        = y0;
            out[ob + (size_t)oc*HWSZ + 8*WW] = y1;
        }
    } else {
        // exact per-channel integer stats: int32 REDUX + int64 shfl reduce
        int warp = t >> 5, lane = t & 31;
        #pragma unroll
        for (int j = 0; j < 8; ++j) {
            int si = __reduce_add_sync(0xFFFFFFFFu, acc0[j] + acc1[j]);
            long long sq = (long long)acc0[j]*(long long)acc0[j]
                         + (long long)acc1[j]*(long long)acc1[j];
            #pragma unroll
            for (int off = 16; off; off >>= 1)
                sq += __shfl_down_sync(0xFFFFFFFFu, sq, off);
            if (lane == 0) { s_I[warp][j] = (long long)si; s_Q[warp][j] = sq; }
        }
        __syncthreads();
        if (t < 16) {
            int grp = t >> 3, ocw = t & 7;   // warps grp*4..grp*4+3 hold oc t
            long long ti = 0, tq = 0;
            #pragma unroll
            for (int wp = 0; wp < 4; ++wp) {
                ti += s_I[grp*4 + wp][ocw];
                tq += s_Q[grp*4 + wp][ocw];
            }
            atomicAdd(&g_sumI[t], (unsigned long long)ti);
            atomicAdd(&g_sumQ[t], (unsigned long long)tq);
        }
    }
}

// ---------------- k_fin: compute BN affine from exact sums ------------------
__global__ void k_fin(const float* __restrict__ gamma, const float* __restrict__ beta) {
    int t = threadIdx.x;
    if (t < 16) {
        double stepx = (double)__fdiv_rn(__uint_as_float(g_maxbits), 127.0f);
        double sc = stepx * (double)g_stepw;      // y = sc * acc (exact)
        double M = (double)NPIX;
        double sumI = (double)(long long)g_sumI[t];
        double sumQ = (double)(long long)g_sumQ[t];
        double mean = sc * sumI / M;
        double ey2  = sc * sc * sumQ / M;
        double var  = ey2 - mean*mean;
        double inv  = (double)gamma[t] / sqrt(var + 1e-5);
        g_scale[t] = (float)(sc * inv);
        g_bias[t]  = (float)((double)beta[t] - mean * inv);
    }
}

// ---------------- launch ----------------------------------------------------
extern "C" void kernel_launch(void* const* d_in, const int* in_sizes, int n_in,
                              void* d_out, int out_size) {
    const float* x     = (const float*)d_in[0];
    const float* wgt   = (const float*)d_in[1];
    const float* gamma = (const float*)d_in[2];
    const float* beta  = (const float*)d_in[3];
    float* out = (float*)d_out;

    k_init<<<1, 256>>>(wgt);
    k_xmax<<<1184, 256>>>((const float4*)x);
    k_xq<<<(NPIX/4 + 255)/256, 256>>>(x);
    dim3 g(GX, GY, NIMG);
    k_conv<false><<<g, 256>>>(nullptr);
    k_fin<<<1, 32>>>(gamma, beta);
    k_conv<true><<<g, 256>>>(out);
}

// round 5
// speedup vs baseline: 1.9460x; 1.1025x over previous
#include <cuda_runtime.h>
#include <cstdint>

// Problem dims
#define NIMG 32
#define CCH 16
#define HH 224
#define WW 224
#define HWSZ (HH*WW)          // 50176
#define NPIX (NIMG*HWSZ)      // 1,605,632 pixels
#define TOTAL (NIMG*CCH*HWSZ) // 25,690,112 elements

// Conv tiling: 16x16 pixel tile, 256 threads (8 warps), implicit GEMM via
// mma.sync m16n8k32 s8: M=16 oc, N=8 px per mma, K=160 (16ch x 10 taps, tap9=0)
#define TH 16
#define TW 16
#define GX (WW/TW)   // 14
#define GY (HH/TH)   // 14

// ---------------- scratch (device globals: no allocations allowed) ----------
__device__ unsigned           g_maxbits;     // max|x| as float bits (all >= 0)
__device__ float              g_stepw;       // weight quant step
__device__ int4               g_wq[16*9];    // packed int8 weights [oc][tap]
__device__ int4               g_xq[NPIX];    // packed int8 activations [n][h][w]
__device__ unsigned long long g_sumI[16];    // exact global sum of acc   (2's comp)
__device__ unsigned long long g_sumQ[16];    // exact global sum of acc^2
__device__ float              g_scale[16];   // fused BN scale (incl. stepx*stepw)
__device__ float              g_bias[16];    // fused BN bias

// ---------------- mma wrapper ----------------------------------------------
__device__ __forceinline__ void mma_s8(int* d, int a0, int a1, int a2, int a3,
                                       int b0, int b1) {
    asm volatile(
        "mma.sync.aligned.m16n8k32.row.col.s32.s8.s8.s32 "
        "{%0,%1,%2,%3},{%4,%5,%6,%7},{%8,%9},{%0,%1,%2,%3};"
        : "+r"(d[0]), "+r"(d[1]), "+r"(d[2]), "+r"(d[3])
        : "r"(a0), "r"(a1), "r"(a2), "r"(a3), "r"(b0), "r"(b1));
}

// ---------------- k_init: reset + weight max + weight quantize/pack ---------
__global__ void k_init(const float* __restrict__ w) {
    __shared__ float red[256];
    __shared__ float s_stepw;
    int t = threadIdx.x;
    if (t == 0) g_maxbits = 0u;
    if (t < 16) { g_sumI[t] = 0ull; g_sumQ[t] = 0ull; }
    float m = 0.f;
    for (int i = t; i < 16*16*9; i += 256) m = fmaxf(m, fabsf(w[i]));
    red[t] = m; __syncthreads();
    for (int s = 128; s; s >>= 1) {
        if (t < s) red[t] = fmaxf(red[t], red[t+s]);
        __syncthreads();
    }
    if (t == 0) {
        float sw = __fdiv_rn(red[0], 127.0f);
        g_stepw = sw; s_stepw = sw;
    }
    __syncthreads();
    float sw = s_stepw;
    if (t < 144) {                       // 16 oc * 9 taps
        int oc = t / 9, tap = t % 9;
        int vals[4];
        #pragma unroll
        for (int g = 0; g < 4; ++g) {
            int packed = 0;
            #pragma unroll
            for (int b = 0; b < 4; ++b) {
                int c = g*4 + b;
                float v = w[(oc*16 + c)*9 + tap];
                float q = rintf(__fdiv_rn(v, sw));
                q = fminf(fmaxf(q, -127.f), 127.f);
                int qi = (int)q;
                packed |= (qi & 0xFF) << (8*b);
            }
            vals[g] = packed;
        }
        g_wq[oc*9 + tap] = make_int4(vals[0], vals[1], vals[2], vals[3]);
    }
}

// ---------------- k_xmax: global max|x| ------------------------------------
__global__ void k_xmax(const float4* __restrict__ x) {
    float m = 0.f;
    int stride = gridDim.x * blockDim.x;
    for (int i = blockIdx.x*blockDim.x + threadIdx.x; i < TOTAL/4; i += stride) {
        float4 v = x[i];
        m = fmaxf(m, fmaxf(fmaxf(fabsf(v.x), fabsf(v.y)), fmaxf(fabsf(v.z), fabsf(v.w))));
    }
    #pragma unroll
    for (int off = 16; off; off >>= 1)
        m = fmaxf(m, __shfl_xor_sync(0xFFFFFFFFu, m, off));
    __shared__ float red[8];
    int lane = threadIdx.x & 31, wp = threadIdx.x >> 5;
    if (lane == 0) red[wp] = m;
    __syncthreads();
    if (threadIdx.x == 0) {
        float mm = red[0];
        #pragma unroll
        for (int i = 1; i < 8; ++i) mm = fmaxf(mm, red[i]);
        atomicMax(&g_maxbits, __float_as_uint(mm));
    }
}

// ---------------- k_xq: quantize x -> packed int8, 4 pixels per thread ------
__global__ void k_xq(const float* __restrict__ x) {
    int p4 = blockIdx.x*blockDim.x + threadIdx.x;
    if (p4 >= NPIX/4) return;
    float sx  = __fdiv_rn(__uint_as_float(g_maxbits), 127.0f);
    float inv = __fdiv_rn(1.0f, sx);
    int n = p4 / (HWSZ/4);
    int rem4 = p4 - n*(HWSZ/4);
    const float* base = x + (size_t)n*(CCH*HWSZ) + rem4*4;
    int out[4][4];   // [pixel][channel-group]
    #pragma unroll
    for (int c = 0; c < 16; ++c) {
        float4 v = *(const float4*)(base + (size_t)c*HWSZ);
        float f[4] = {v.x, v.y, v.z, v.w};
        int g = c >> 2, b = c & 3;
        #pragma unroll
        for (int px = 0; px < 4; ++px) {
            float q = rintf(f[px] * inv);
            q = fminf(fmaxf(q, -127.f), 127.f);
            int qi = (int)q;
            if (b == 0) out[px][g] = (qi & 0xFF);
            else out[px][g] |= (qi & 0xFF) << (8*b);
        }
    }
    int pix = n*HWSZ + rem4*4;
    #pragma unroll
    for (int px = 0; px < 4; ++px)
        g_xq[pix + px] = make_int4(out[px][0], out[px][1], out[px][2], out[px][3]);
}

// ---------------- conv: tensor-core implicit GEMM ---------------------------
// Warp w handles pixel rows {2w, 2w+1} x 16 cols = 4 mma n-tiles of 8 px.
// K order: k = tap*16 + ch; chunk kc covers taps {2kc, 2kc+1}; tap 9 weights=0.
template<bool WRITE>
__global__ void __launch_bounds__(256, 4) k_conv(float* __restrict__ out) {
    __shared__ int4 s_x[18][18];        // halo tile, pixel-major, 5184 B
    __shared__ int4 s_w[160];           // [oc][tap0..9], 2560 B
    __shared__ int       s_I[8][16];
    __shared__ long long s_Q[8][16];

    int t = threadIdx.x;
    int n = blockIdx.z;
    int h0 = blockIdx.y * TH, w0 = blockIdx.x * TW;

    // load halo tile (zero padded)
    for (int i = t; i < 18*18; i += 256) {
        int r = i / 18, cc = i - r*18;
        int gh = h0 - 1 + r, gw = w0 - 1 + cc;
        int4 v = make_int4(0,0,0,0);
        if ((unsigned)gh < (unsigned)HH && (unsigned)gw < (unsigned)WW)
            v = g_xq[n*HWSZ + gh*WW + gw];
        s_x[r][cc] = v;
    }
    if (t < 160) {
        int oc = t / 10, tap = t - oc*10;
        s_w[t] = (tap < 9) ? g_wq[oc*9 + tap] : make_int4(0,0,0,0);
    }
    __syncthreads();

    int w = t >> 5, l = t & 31;
    int g4 = l >> 2, q = l & 3;          // A/C row group, K word index
    const int* swi = (const int*)s_w;

    int acc[4][4];
    #pragma unroll
    for (int tt = 0; tt < 4; ++tt)
        #pragma unroll
        for (int j = 0; j < 4; ++j) acc[tt][j] = 0;

    #pragma unroll
    for (int kc = 0; kc < 5; ++kc) {
        const int tap0 = 2*kc, tap1 = 2*kc + 1;
        const int dy0 = tap0/3,              dx0 = tap0%3;
        const int dy1 = (tap1 < 9) ? tap1/3 : 2, dx1 = (tap1 < 9) ? tap1%3 : 2;
        int a0 = swi[(g4*10      + tap0)*4 + q];
        int a1 = swi[((g4+8)*10  + tap0)*4 + q];
        int a2 = swi[(g4*10      + tap1)*4 + q];
        int a3 = swi[((g4+8)*10  + tap1)*4 + q];
        #pragma unroll
        for (int tt = 0; tt < 4; ++tt) {
            int r0 = 2*w + (tt & 1), c0 = 8*(tt >> 1);
            const int* bp0 = (const int*)&s_x[r0 + dy0][c0 + dx0];
            const int* bp1 = (const int*)&s_x[r0 + dy1][c0 + dx1];
            int b0 = bp0[l];             // coalesced, conflict-free
            int b1 = bp1[l];
            mma_s8(acc[tt], a0, a1, a2, a3, b0, b1);
        }
    }

    if (WRITE) {
        float sc_lo = g_scale[g4],   bi_lo = g_bias[g4];
        float sc_hi = g_scale[g4+8], bi_hi = g_bias[g4+8];
        #pragma unroll
        for (int tt = 0; tt < 4; ++tt) {
            int r0 = 2*w + (tt & 1), c0 = 8*(tt >> 1);
            int h = h0 + r0, wc = w0 + c0 + 2*q;
            size_t ob = (size_t)n*CCH*HWSZ + (size_t)h*WW + wc;
            float2 v0, v1;
            v0.x = fminf(fmaxf(fmaf((float)acc[tt][0], sc_lo, bi_lo), 0.f), 6.f);
            v0.y = fminf(fmaxf(fmaf((float)acc[tt][1], sc_lo, bi_lo), 0.f), 6.f);
            v1.x = fminf(fmaxf(fmaf((float)acc[tt][2], sc_hi, bi_hi), 0.f), 6.f);
            v1.y = fminf(fmaxf(fmaf((float)acc[tt][3], sc_hi, bi_hi), 0.f), 6.f);
            *(float2*)(out + ob + (size_t)g4*HWSZ)     = v0;
            *(float2*)(out + ob + (size_t)(g4+8)*HWSZ) = v1;
        }
    } else {
        // exact per-channel integer stats
        int sl = 0, sh = 0;
        long long ql = 0, qh = 0;
        #pragma unroll
        for (int tt = 0; tt < 4; ++tt) {
            sl += acc[tt][0] + acc[tt][1];
            sh += acc[tt][2] + acc[tt][3];
            ql += (long long)acc[tt][0]*acc[tt][0] + (long long)acc[tt][1]*acc[tt][1];
            qh += (long long)acc[tt][2]*acc[tt][2] + (long long)acc[tt][3]*acc[tt][3];
        }
        // reduce across the 4 lanes sharing each oc (quad = lanes g4*4..g4*4+3)
        sl += __shfl_xor_sync(0xFFFFFFFFu, sl, 1);
        sl += __shfl_xor_sync(0xFFFFFFFFu, sl, 2);
        sh += __shfl_xor_sync(0xFFFFFFFFu, sh, 1);
        sh += __shfl_xor_sync(0xFFFFFFFFu, sh, 2);
        ql += __shfl_xor_sync(0xFFFFFFFFu, ql, 1);
        ql += __shfl_xor_sync(0xFFFFFFFFu, ql, 2);
        qh += __shfl_xor_sync(0xFFFFFFFFu, qh, 1);
        qh += __shfl_xor_sync(0xFFFFFFFFu, qh, 2);
        if (q == 0) {
            s_I[w][g4]     = sl;  s_Q[w][g4]     = ql;
            s_I[w][g4 + 8] = sh;  s_Q[w][g4 + 8] = qh;
        }
        __syncthreads();
        if (t < 16) {
            long long ti = 0, tq = 0;
            #pragma unroll
            for (int wp = 0; wp < 8; ++wp) {
                ti += (long long)s_I[wp][t];
                tq += s_Q[wp][t];
            }
            atomicAdd(&g_sumI[t], (unsigned long long)ti);
            atomicAdd(&g_sumQ[t], (unsigned long long)tq);
        }
    }
}

// ---------------- k_fin: compute BN affine from exact sums ------------------
__global__ void k_fin(const float* __restrict__ gamma, const float* __restrict__ beta) {
    int t = threadIdx.x;
    if (t < 16) {
        double stepx = (double)__fdiv_rn(__uint_as_float(g_maxbits), 127.0f);
        double sc = stepx * (double)g_stepw;      // y = sc * acc (exact)
        double M = (double)NPIX;
        double sumI = (double)(long long)g_sumI[t];
        double sumQ = (double)(long long)g_sumQ[t];
        double mean = sc * sumI / M;
        double ey2  = sc * sc * sumQ / M;
        double var  = ey2 - mean*mean;
        double inv  = (double)gamma[t] / sqrt(var + 1e-5);
        g_scale[t] = (float)(sc * inv);
        g_bias[t]  = (float)((double)beta[t] - mean * inv);
    }
}

// ---------------- launch ----------------------------------------------------
extern "C" void kernel_launch(void* const* d_in, const int* in_sizes, int n_in,
                              void* d_out, int out_size) {
    const float* x     = (const float*)d_in[0];
    const float* wgt   = (const float*)d_in[1];
    const float* gamma = (const float*)d_in[2];
    const float* beta  = (const float*)d_in[3];
    float* out = (float*)d_out;

    k_init<<<1, 256>>>(wgt);
    k_xmax<<<1184, 256>>>((const float4*)x);
    k_xq<<<(NPIX/4 + 255)/256, 256>>>(x);
    dim3 g(GX, GY, NIMG);
    k_conv<false><<<g, 256>>>(nullptr);
    k_fin<<<1, 32>>>(gamma, beta);
    k_conv<true><<<g, 256>>>(out);
}

// round 6
// speedup vs baseline: 2.2712x; 1.1671x over previous
#include <cuda_runtime.h>
#include <cstdint>

// Problem dims
#define NIMG 32
#define CCH 16
#define HH 224
#define WW 224
#define HWSZ (HH*WW)          // 50176
#define NPIX (NIMG*HWSZ)      // 1,605,632 pixels
#define TOTAL (NIMG*CCH*HWSZ) // 25,690,112 elements

// Conv tiling: 16x16 pixel tile, 256 threads (8 warps), implicit GEMM via
// mma.sync m16n8k32 s8: M=16 oc, N=8 px per mma, K=160 (16ch x 10 taps, tap9=0)
#define TH 16
#define TW 16
#define GX (WW/TW)   // 14
#define GY (HH/TH)   // 14

// ---------------- scratch (device globals: no allocations allowed) ----------
__device__ unsigned           g_maxbits;     // max|x| as float bits (all >= 0)
__device__ float              g_stepw;       // weight quant step
__device__ int4               g_wq[16*9];    // packed int8 weights [oc][tap]
__device__ int4               g_xq[NPIX];    // packed int8 activations [n][h][w]
__device__ int                g_acc[TOTAL];  // raw conv accumulators (int32, NCHW)
__device__ unsigned long long g_sumI[16];    // exact global sum of acc   (2's comp)
__device__ unsigned long long g_sumQ[16];    // exact global sum of acc^2
__device__ float              g_scale[16];   // fused BN scale (incl. stepx*stepw)
__device__ float              g_bias[16];    // fused BN bias

// ---------------- mma wrapper ----------------------------------------------
__device__ __forceinline__ void mma_s8(int* d, int a0, int a1, int a2, int a3,
                                       int b0, int b1) {
    asm volatile(
        "mma.sync.aligned.m16n8k32.row.col.s32.s8.s8.s32 "
        "{%0,%1,%2,%3},{%4,%5,%6,%7},{%8,%9},{%0,%1,%2,%3};"
        : "+r"(d[0]), "+r"(d[1]), "+r"(d[2]), "+r"(d[3])
        : "r"(a0), "r"(a1), "r"(a2), "r"(a3), "r"(b0), "r"(b1));
}

// ---------------- k_init: reset + weight max + weight quantize/pack ---------
__global__ void k_init(const float* __restrict__ w) {
    __shared__ float red[256];
    __shared__ float s_stepw;
    int t = threadIdx.x;
    if (t == 0) g_maxbits = 0u;
    if (t < 16) { g_sumI[t] = 0ull; g_sumQ[t] = 0ull; }
    float m = 0.f;
    for (int i = t; i < 16*16*9; i += 256) m = fmaxf(m, fabsf(w[i]));
    red[t] = m; __syncthreads();
    for (int s = 128; s; s >>= 1) {
        if (t < s) red[t] = fmaxf(red[t], red[t+s]);
        __syncthreads();
    }
    if (t == 0) {
        float sw = __fdiv_rn(red[0], 127.0f);
        g_stepw = sw; s_stepw = sw;
    }
    __syncthreads();
    float sw = s_stepw;
    if (t < 144) {                       // 16 oc * 9 taps
        int oc = t / 9, tap = t % 9;
        int vals[4];
        #pragma unroll
        for (int g = 0; g < 4; ++g) {
            int packed = 0;
            #pragma unroll
            for (int b = 0; b < 4; ++b) {
                int c = g*4 + b;
                float v = w[(oc*16 + c)*9 + tap];
                float q = rintf(__fdiv_rn(v, sw));
                q = fminf(fmaxf(q, -127.f), 127.f);
                int qi = (int)q;
                packed |= (qi & 0xFF) << (8*b);
            }
            vals[g] = packed;
        }
        g_wq[oc*9 + tap] = make_int4(vals[0], vals[1], vals[2], vals[3]);
    }
}

// ---------------- k_xmax: global max|x| ------------------------------------
__global__ void k_xmax(const float4* __restrict__ x) {
    float m = 0.f;
    int stride = gridDim.x * blockDim.x;
    for (int i = blockIdx.x*blockDim.x + threadIdx.x; i < TOTAL/4; i += stride) {
        float4 v = x[i];
        m = fmaxf(m, fmaxf(fmaxf(fabsf(v.x), fabsf(v.y)), fmaxf(fabsf(v.z), fabsf(v.w))));
    }
    #pragma unroll
    for (int off = 16; off; off >>= 1)
        m = fmaxf(m, __shfl_xor_sync(0xFFFFFFFFu, m, off));
    __shared__ float red[8];
    int lane = threadIdx.x & 31, wp = threadIdx.x >> 5;
    if (lane == 0) red[wp] = m;
    __syncthreads();
    if (threadIdx.x == 0) {
        float mm = red[0];
        #pragma unroll
        for (int i = 1; i < 8; ++i) mm = fmaxf(mm, red[i]);
        atomicMax(&g_maxbits, __float_as_uint(mm));
    }
}

// ---------------- k_xq: quantize x -> packed int8, 4 pixels per thread ------
__global__ void k_xq(const float* __restrict__ x) {
    int p4 = blockIdx.x*blockDim.x + threadIdx.x;
    if (p4 >= NPIX/4) return;
    float sx  = __fdiv_rn(__uint_as_float(g_maxbits), 127.0f);
    float inv = __fdiv_rn(1.0f, sx);
    int n = p4 / (HWSZ/4);
    int rem4 = p4 - n*(HWSZ/4);
    const float* base = x + (size_t)n*(CCH*HWSZ) + rem4*4;
    int out[4][4];   // [pixel][channel-group]
    #pragma unroll
    for (int c = 0; c < 16; ++c) {
        float4 v = *(const float4*)(base + (size_t)c*HWSZ);
        float f[4] = {v.x, v.y, v.z, v.w};
        int g = c >> 2, b = c & 3;
        #pragma unroll
        for (int px = 0; px < 4; ++px) {
            float q = rintf(f[px] * inv);
            q = fminf(fmaxf(q, -127.f), 127.f);
            int qi = (int)q;
            if (b == 0) out[px][g] = (qi & 0xFF);
            else out[px][g] |= (qi & 0xFF) << (8*b);
        }
    }
    int pix = n*HWSZ + rem4*4;
    #pragma unroll
    for (int px = 0; px < 4; ++px)
        g_xq[pix + px] = make_int4(out[px][0], out[px][1], out[px][2], out[px][3]);
}

// ---------------- conv: tensor-core implicit GEMM, ONE pass -----------------
// Computes acc, stores raw int32 acc to g_acc (hidden under tensor work),
// and accumulates exact global BN statistics.
__global__ void __launch_bounds__(256, 4) k_conv() {
    __shared__ int4 s_x[18][18];        // halo tile, pixel-major, 5184 B
    __shared__ int4 s_w[160];           // [oc][tap0..9], 2560 B
    __shared__ int       s_I[8][16];
    __shared__ long long s_Q[8][16];

    int t = threadIdx.x;
    int n = blockIdx.z;
    int h0 = blockIdx.y * TH, w0 = blockIdx.x * TW;

    // load halo tile (zero padded)
    for (int i = t; i < 18*18; i += 256) {
        int r = i / 18, cc = i - r*18;
        int gh = h0 - 1 + r, gw = w0 - 1 + cc;
        int4 v = make_int4(0,0,0,0);
        if ((unsigned)gh < (unsigned)HH && (unsigned)gw < (unsigned)WW)
            v = g_xq[n*HWSZ + gh*WW + gw];
        s_x[r][cc] = v;
    }
    if (t < 160) {
        int oc = t / 10, tap = t - oc*10;
        s_w[t] = (tap < 9) ? g_wq[oc*9 + tap] : make_int4(0,0,0,0);
    }
    __syncthreads();

    int w = t >> 5, l = t & 31;
    int g4 = l >> 2, q = l & 3;          // A/C row group, K word index
    const int* swi = (const int*)s_w;

    int acc[4][4];
    #pragma unroll
    for (int tt = 0; tt < 4; ++tt)
        #pragma unroll
        for (int j = 0; j < 4; ++j) acc[tt][j] = 0;

    #pragma unroll
    for (int kc = 0; kc < 5; ++kc) {
        const int tap0 = 2*kc, tap1 = 2*kc + 1;
        const int dy0 = tap0/3,              dx0 = tap0%3;
        const int dy1 = (tap1 < 9) ? tap1/3 : 2, dx1 = (tap1 < 9) ? tap1%3 : 2;
        int a0 = swi[(g4*10      + tap0)*4 + q];
        int a1 = swi[((g4+8)*10  + tap0)*4 + q];
        int a2 = swi[(g4*10      + tap1)*4 + q];
        int a3 = swi[((g4+8)*10  + tap1)*4 + q];
        #pragma unroll
        for (int tt = 0; tt < 4; ++tt) {
            int r0 = 2*w + (tt & 1), c0 = 8*(tt >> 1);
            const int* bp0 = (const int*)&s_x[r0 + dy0][c0 + dx0];
            const int* bp1 = (const int*)&s_x[r0 + dy1][c0 + dx1];
            int b0 = bp0[l];             // coalesced, conflict-free
            int b1 = bp1[l];
            mma_s8(acc[tt], a0, a1, a2, a3, b0, b1);
        }
    }

    // store raw accumulators (int2 per oc-half, coalesced 32B per quad)
    #pragma unroll
    for (int tt = 0; tt < 4; ++tt) {
        int r0 = 2*w + (tt & 1), c0 = 8*(tt >> 1);
        int h = h0 + r0, wc = w0 + c0 + 2*q;
        size_t ob = (size_t)n*CCH*HWSZ + (size_t)h*WW + wc;
        *(int2*)(g_acc + ob + (size_t)g4*HWSZ)     = make_int2(acc[tt][0], acc[tt][1]);
        *(int2*)(g_acc + ob + (size_t)(g4+8)*HWSZ) = make_int2(acc[tt][2], acc[tt][3]);
    }

    // exact per-channel integer stats
    int sl = 0, sh = 0;
    long long ql = 0, qh = 0;
    #pragma unroll
    for (int tt = 0; tt < 4; ++tt) {
        sl += acc[tt][0] + acc[tt][1];
        sh += acc[tt][2] + acc[tt][3];
        ql += (long long)acc[tt][0]*acc[tt][0] + (long long)acc[tt][1]*acc[tt][1];
        qh += (long long)acc[tt][2]*acc[tt][2] + (long long)acc[tt][3]*acc[tt][3];
    }
    sl += __shfl_xor_sync(0xFFFFFFFFu, sl, 1);
    sl += __shfl_xor_sync(0xFFFFFFFFu, sl, 2);
    sh += __shfl_xor_sync(0xFFFFFFFFu, sh, 1);
    sh += __shfl_xor_sync(0xFFFFFFFFu, sh, 2);
    ql += __shfl_xor_sync(0xFFFFFFFFu, ql, 1);
    ql += __shfl_xor_sync(0xFFFFFFFFu, ql, 2);
    qh += __shfl_xor_sync(0xFFFFFFFFu, qh, 1);
    qh += __shfl_xor_sync(0xFFFFFFFFu, qh, 2);
    if (q == 0) {
        s_I[w][g4]     = sl;  s_Q[w][g4]     = ql;
        s_I[w][g4 + 8] = sh;  s_Q[w][g4 + 8] = qh;
    }
    __syncthreads();
    if (t < 16) {
        long long ti = 0, tq = 0;
        #pragma unroll
        for (int wp = 0; wp < 8; ++wp) {
            ti += (long long)s_I[wp][t];
            tq += s_Q[wp][t];
        }
        atomicAdd(&g_sumI[t], (unsigned long long)ti);
        atomicAdd(&g_sumQ[t], (unsigned long long)tq);
    }
}

// ---------------- k_fin: compute BN affine from exact sums ------------------
__global__ void k_fin(const float* __restrict__ gamma, const float* __restrict__ beta) {
    int t = threadIdx.x;
    if (t < 16) {
        double stepx = (double)__fdiv_rn(__uint_as_float(g_maxbits), 127.0f);
        double sc = stepx * (double)g_stepw;      // y = sc * acc (exact)
        double M = (double)NPIX;
        double sumI = (double)(long long)g_sumI[t];
        double sumQ = (double)(long long)g_sumQ[t];
        double mean = sc * sumI / M;
        double ey2  = sc * sc * sumQ / M;
        double var  = ey2 - mean*mean;
        double inv  = (double)gamma[t] / sqrt(var + 1e-5);
        g_scale[t] = (float)(sc * inv);
        g_bias[t]  = (float)((double)beta[t] - mean * inv);
    }
}

// ---------------- k_epi: memory-bound affine epilogue -----------------------
// grid (HWSZ/4/256 = 49, NIMG*CCH = 512); one int4 of acc -> one float4 of out
__global__ void k_epi(float* __restrict__ out) {
    int plane = blockIdx.y;              // n*16 + c
    int c = plane & 15;
    float sc = g_scale[c], bi = g_bias[c];
    int i = blockIdx.x * blockDim.x + threadIdx.x;   // 0..12543
    size_t base = (size_t)plane * HWSZ + (size_t)i * 4;
    int4 a = *(const int4*)(g_acc + base);
    float4 v;
    v.x = fminf(fmaxf(fmaf((float)a.x, sc, bi), 0.f), 6.f);
    v.y = fminf(fmaxf(fmaf((float)a.y, sc, bi), 0.f), 6.f);
    v.z = fminf(fmaxf(fmaf((float)a.z, sc, bi), 0.f), 6.f);
    v.w = fminf(fmaxf(fmaf((float)a.w, sc, bi), 0.f), 6.f);
    *(float4*)(out + base) = v;
}

// ---------------- launch ----------------------------------------------------
extern "C" void kernel_launch(void* const* d_in, const int* in_sizes, int n_in,
                              void* d_out, int out_size) {
    const float* x     = (const float*)d_in[0];
    const float* wgt   = (const float*)d_in[1];
    const float* gamma = (const float*)d_in[2];
    const float* beta  = (const float*)d_in[3];
    float* out = (float*)d_out;

    k_init<<<1, 256>>>(wgt);
    k_xmax<<<1184, 256>>>((const float4*)x);
    k_xq<<<(NPIX/4 + 255)/256, 256>>>(x);
    dim3 g(GX, GY, NIMG);
    k_conv<<<g, 256>>>();
    k_fin<<<1, 32>>>(gamma, beta);
    dim3 ge(HWSZ/4/256, NIMG*CCH);       // (49, 512)
    k_epi<<<ge, 256>>>(out);
}